// round 3
// baseline (speedup 1.0000x reference)
#include <cuda_runtime.h>
#include <cuda_bf16.h>
#include <cstdint>
#include <cstddef>

// ---------------------------------------------------------------------------
// LiquidNeuralNetwork (CfC / AutoNCP).
//  * ta/tb gates merged (sigmoid(a+b)) -> 3 gate matrices instead of 4
//  * per layer: parallel input-part GEMM over all (b,t), then a sequential
//    recurrent pass with merged recurrent weights resident in SMEM.
// ---------------------------------------------------------------------------

#define TSTEPS 1024
#define NBATCH 256
#define MROWS  (NBATCH * TSTEPS)

// layer dims: U = units, FIN = layer input, NG = 3*U gates, NGP padded (even),
// UP = padded hidden
#define U0 135
#define FIN0 128
#define NG0 405
#define NGP0 408
#define UP0 136

#define U1 89
#define FIN1 135
#define NG1 267
#define NGP1 272
#define UP1 96

#define U2 32
#define FIN2 89
#define NG2 96
#define NGP2 96
#define UP2 32

// ---------------- scratch (device globals; no allocations allowed) ---------
__device__ float g_G0[(size_t)MROWS * NGP0];
__device__ float g_H0[(size_t)MROWS * U0];
__device__ float g_G1[(size_t)MROWS * NGP1];
__device__ float g_H1[(size_t)MROWS * U1];
__device__ float g_G2[(size_t)MROWS * NGP2];
__device__ float g_H2[(size_t)MROWS * U2];

__device__ float g_Wx0[FIN0 * NGP0];
__device__ float g_Wh0[UP0 * NGP0];
__device__ float g_b0[NGP0];
__device__ float g_Wx1[FIN1 * NGP1];
__device__ float g_Wh1[UP1 * NGP1];
__device__ float g_b1[NGP1];
__device__ float g_Wx2[FIN2 * NGP2];
__device__ float g_Wh2[UP2 * NGP2];
__device__ float g_b2[NGP2];
__device__ float g_fcwT[32 * 32];

// ---------------------------------------------------------------------------
// Weight prep: fold mask into ff1/ff2 input block, merge ta+tb, transpose to
// [k][n] with zero padding. Gate order n: [0,U)=ff1, [U,2U)=ff2, [2U,3U)=s.
// ---------------------------------------------------------------------------
template<int U, int FIN, int NG, int NGP, int UP>
__global__ void prep_layer(const float* __restrict__ ff1w, const float* __restrict__ ff1b,
                           const float* __restrict__ ff2w, const float* __restrict__ ff2b,
                           const float* __restrict__ taw,  const float* __restrict__ tab,
                           const float* __restrict__ tbw,  const float* __restrict__ tbb,
                           const int*   __restrict__ mask,
                           float* __restrict__ Wx, float* __restrict__ Wh,
                           float* __restrict__ bias) {
    const int C = FIN + U;
    const int stride = gridDim.x * blockDim.x;
    const int g0 = blockIdx.x * blockDim.x + threadIdx.x;

    for (int i = g0; i < FIN * NGP; i += stride) {
        int k = i / NGP, n = i % NGP;
        float v = 0.f;
        if (n < U)          v = ff1w[n * C + k] * (float)mask[n * C + k];
        else if (n < 2 * U) v = ff2w[(n - U) * C + k] * (float)mask[(n - U) * C + k];
        else if (n < NG)    v = taw[(n - 2 * U) * C + k] + tbw[(n - 2 * U) * C + k];
        Wx[i] = v;
    }
    for (int i = g0; i < UP * NGP; i += stride) {
        int k = i / NGP, n = i % NGP;
        float v = 0.f;
        if (k < U) {   // recurrent block of the NCP mask is all-ones
            if (n < U)          v = ff1w[n * C + FIN + k];
            else if (n < 2 * U) v = ff2w[(n - U) * C + FIN + k];
            else if (n < NG)    v = taw[(n - 2 * U) * C + FIN + k] + tbw[(n - 2 * U) * C + FIN + k];
        }
        Wh[i] = v;
    }
    for (int i = g0; i < NGP; i += stride) {
        float v = 0.f;
        if (i < U)          v = ff1b[i];
        else if (i < 2 * U) v = ff2b[i - U];
        else if (i < NG)    v = tab[i - 2 * U] + tbb[i - 2 * U];
        bias[i] = v;
    }
}

__global__ void prep_fc(const float* __restrict__ fcw, float* __restrict__ out) {
    int i = threadIdx.x;              // 1024 threads
    int o = i >> 5, k = i & 31;
    out[k * 32 + o] = fcw[o * 32 + k];
}

// ---------------------------------------------------------------------------
// GEMM + bias: C[m,n] = sum_k A[m,k]*Bt[k,n] + bias[n].
// BM=BN=64, BK=32, 256 threads, 4x4 per-thread microtile. M % 64 == 0.
// ---------------------------------------------------------------------------
__global__ __launch_bounds__(256)
void gemm_bias(const float* __restrict__ A, int lda,
               const float* __restrict__ Bt, int ldb,
               const float* __restrict__ bias,
               float* __restrict__ C, int ldc,
               int N, int K) {
    __shared__ float sA[32][68];
    __shared__ float sB[32][68];
    const int bm = blockIdx.y * 64;
    const int bn = blockIdx.x * 64;
    const int tid = threadIdx.x;
    const int tm = (tid >> 4) << 2;
    const int tn = (tid & 15) << 2;
    float acc[4][4] = {};

    for (int k0 = 0; k0 < K; k0 += 32) {
#pragma unroll
        for (int i = 0; i < 8; ++i) {
            int e = tid + i * 256;
            int m = e >> 5, kk = e & 31;
            int k = k0 + kk;
            sA[kk][m] = (k < K) ? A[(size_t)(bm + m) * lda + k] : 0.f;
        }
#pragma unroll
        for (int i = 0; i < 8; ++i) {
            int e = tid + i * 256;
            int kk = e >> 6, n = e & 63;
            int k = k0 + kk;
            sB[kk][n] = (k < K && (bn + n) < N) ? Bt[(size_t)k * ldb + bn + n] : 0.f;
        }
        __syncthreads();
#pragma unroll
        for (int kk = 0; kk < 32; ++kk) {
            float4 a = *(const float4*)&sA[kk][tm];
            float4 b = *(const float4*)&sB[kk][tn];
            float av[4] = {a.x, a.y, a.z, a.w};
            float bv[4] = {b.x, b.y, b.z, b.w};
#pragma unroll
            for (int i = 0; i < 4; ++i)
#pragma unroll
                for (int j = 0; j < 4; ++j)
                    acc[i][j] += av[i] * bv[j];
        }
        __syncthreads();
    }
#pragma unroll
    for (int i = 0; i < 4; ++i)
#pragma unroll
        for (int j = 0; j < 4; ++j) {
            int n = bn + tn + j;
            if (n < N)
                C[(size_t)(bm + tm + i) * ldc + n] = acc[i][j] + bias[n];
        }
}

// ---------------------------------------------------------------------------
// Recurrent pass: one CTA per 2 batch rows; merged recurrent weights resident
// in SMEM for the whole T loop. Gate inputs G loaded early, added after the
// matvec (hides DRAM latency behind ~1700 cycles of SMEM compute).
//   gate[n] = G[b,t,n] + sum_k h[k]*Wh[k][n]
//   h'[u]   = tanh(g[u])*(1-s) + s*tanh(g[u+U]),  s = sigmoid(g[u+2U])
// ---------------------------------------------------------------------------
template<int U, int UP, int NG, int NGP, int THREADS>
__global__ __launch_bounds__(THREADS)
void rec_kernel(const float* __restrict__ G, const float* __restrict__ Wg,
                float* __restrict__ H) {
    extern __shared__ float smem[];
    float* sW = smem;                  // [UP*NGP]
    float* sh = sW + UP * NGP;         // [2*UP]
    float* sg = sh + 2 * UP;           // [2*NGP]
    const int tid = threadIdx.x;
    const int bb0 = blockIdx.x * 2;

    for (int i = tid; i < UP * NGP; i += THREADS) sW[i] = Wg[i];
    for (int i = tid; i < 2 * UP; i += THREADS) sh[i] = 0.f;
    __syncthreads();

    constexpr int P = (NG + 1) / 2;
    const bool act = tid < P;
    const int n0 = tid * 2;
    const float* Gp0 = G + (size_t)bb0 * TSTEPS * NGP + n0;
    const float* Gp1 = Gp0 + (size_t)TSTEPS * NGP;
    float* Hp = H + (size_t)bb0 * TSTEPS * U;

    for (int t = 0; t < TSTEPS; ++t) {
        if (act) {
            float2 ga = *(const float2*)Gp0;
            float2 gb = *(const float2*)Gp1;
            float a0 = 0.f, a1 = 0.f, c0 = 0.f, c1 = 0.f;
#pragma unroll 5
            for (int k = 0; k < U; ++k) {
                float2 w = *(const float2*)&sW[k * NGP + n0];
                float h0 = sh[k], h1 = sh[UP + k];
                a0 += w.x * h0; a1 += w.y * h0;
                c0 += w.x * h1; c1 += w.y * h1;
            }
            sg[n0] = a0 + ga.x;       sg[n0 + 1] = a1 + ga.y;
            sg[NGP + n0] = c0 + gb.x; sg[NGP + n0 + 1] = c1 + gb.y;
        }
        __syncthreads();
        for (int i = tid; i < 2 * U; i += THREADS) {
            int bb = (i < U) ? 0 : 1;
            int u = i - bb * U;
            float f1 = tanhf(sg[bb * NGP + u]);
            float f2 = tanhf(sg[bb * NGP + u + U]);
            float sv = sg[bb * NGP + u + 2 * U];
            float sig = 1.f / (1.f + expf(-sv));
            float hn = f1 * (1.f - sig) + sig * f2;
            sh[bb * UP + u] = hn;
            Hp[((size_t)bb * TSTEPS + t) * U + u] = hn;
        }
        __syncthreads();
        Gp0 += NGP; Gp1 += NGP;
    }
}

// ---------------------------------------------------------------------------
// host side
// ---------------------------------------------------------------------------
static float* dev_addr(const void* sym) {
    void* p = nullptr;
    cudaGetSymbolAddress(&p, sym);
    return (float*)p;
}

extern "C" void kernel_launch(void* const* d_in, const int* in_sizes, int n_in,
                              void* d_out, int out_size) {
    // Resolve input ordering: dict order has mask0 (35505 ints) at index 9,
    // signature order has l1_ff1_w (19936 floats) there.
    int L0 = 1, M0, L1, M1, L2, M2, FCW, FCB;
    if (in_sizes[9] == 19936) {            // signature order
        L1 = 9; L2 = 17; FCW = 25; FCB = 26; M0 = 27; M1 = 28; M2 = 29;
    } else {                               // dict order
        M0 = 9; L1 = 10; M1 = 18; L2 = 19; M2 = 27; FCW = 28; FCB = 29;
    }

    const float* X = (const float*)d_in[0];
    float* OUT = (float*)d_out;

    float* G0 = dev_addr(g_G0); float* H0 = dev_addr(g_H0);
    float* G1 = dev_addr(g_G1); float* H1 = dev_addr(g_H1);
    float* G2 = dev_addr(g_G2); float* H2 = dev_addr(g_H2);
    float* Wx0 = dev_addr(g_Wx0); float* Wh0 = dev_addr(g_Wh0); float* B0 = dev_addr(g_b0);
    float* Wx1 = dev_addr(g_Wx1); float* Wh1 = dev_addr(g_Wh1); float* B1 = dev_addr(g_b1);
    float* Wx2 = dev_addr(g_Wx2); float* Wh2 = dev_addr(g_Wh2); float* B2 = dev_addr(g_b2);
    float* FcT = dev_addr(g_fcwT);

    // opt-in SMEM for the big recurrent kernels
    static bool attr_done = false;
    if (!attr_done) {
        cudaFuncSetAttribute((const void*)rec_kernel<U0, UP0, NG0, NGP0, 256>,
                             cudaFuncAttributeMaxDynamicSharedMemorySize, 230000);
        cudaFuncSetAttribute((const void*)rec_kernel<U1, UP1, NG1, NGP1, 192>,
                             cudaFuncAttributeMaxDynamicSharedMemorySize, 120000);
        attr_done = true;
    }

    // ---- weight prep ----
    prep_layer<U0, FIN0, NG0, NGP0, UP0><<<128, 256>>>(
        (const float*)d_in[L0 + 0], (const float*)d_in[L0 + 1],
        (const float*)d_in[L0 + 2], (const float*)d_in[L0 + 3],
        (const float*)d_in[L0 + 4], (const float*)d_in[L0 + 5],
        (const float*)d_in[L0 + 6], (const float*)d_in[L0 + 7],
        (const int*)d_in[M0], Wx0, Wh0, B0);
    prep_layer<U1, FIN1, NG1, NGP1, UP1><<<128, 256>>>(
        (const float*)d_in[L1 + 0], (const float*)d_in[L1 + 1],
        (const float*)d_in[L1 + 2], (const float*)d_in[L1 + 3],
        (const float*)d_in[L1 + 4], (const float*)d_in[L1 + 5],
        (const float*)d_in[L1 + 6], (const float*)d_in[L1 + 7],
        (const int*)d_in[M1], Wx1, Wh1, B1);
    prep_layer<U2, FIN2, NG2, NGP2, UP2><<<64, 256>>>(
        (const float*)d_in[L2 + 0], (const float*)d_in[L2 + 1],
        (const float*)d_in[L2 + 2], (const float*)d_in[L2 + 3],
        (const float*)d_in[L2 + 4], (const float*)d_in[L2 + 5],
        (const float*)d_in[L2 + 6], (const float*)d_in[L2 + 7],
        (const int*)d_in[M2], Wx2, Wh2, B2);
    prep_fc<<<1, 1024>>>((const float*)d_in[FCW], FcT);

    const dim3 gthr(256);
    const int MB = MROWS / 64;   // 4096

    // ---- layer 0 ----
    gemm_bias<<<dim3((NGP0 + 63) / 64, MB), gthr>>>(X, FIN0, Wx0, NGP0, B0, G0, NGP0, NGP0, FIN0);
    {
        size_t sm = (size_t)(UP0 * NGP0 + 2 * UP0 + 2 * NGP0) * 4;
        rec_kernel<U0, UP0, NG0, NGP0, 256><<<NBATCH / 2, 256, sm>>>(G0, Wh0, H0);
    }
    // ---- layer 1 ----
    gemm_bias<<<dim3((NGP1 + 63) / 64, MB), gthr>>>(H0, U0, Wx1, NGP1, B1, G1, NGP1, NGP1, U0);
    {
        size_t sm = (size_t)(UP1 * NGP1 + 2 * UP1 + 2 * NGP1) * 4;
        rec_kernel<U1, UP1, NG1, NGP1, 192><<<NBATCH / 2, 192, sm>>>(G1, Wh1, H1);
    }
    // ---- layer 2 ----
    gemm_bias<<<dim3((NGP2 + 63) / 64, MB), gthr>>>(H1, U1, Wx2, NGP2, B2, G2, NGP2, NGP2, U1);
    {
        size_t sm = (size_t)(UP2 * NGP2 + 2 * UP2 + 2 * NGP2) * 4;
        rec_kernel<U2, UP2, NG2, NGP2, 96><<<NBATCH / 2, 96, sm>>>(G2, Wh2, H2);
    }
    // ---- final FC (pool is identity since MOT == OUT) ----
    gemm_bias<<<dim3(1, MB), gthr>>>(H2, U2, FcT, 32, (const float*)d_in[FCB], OUT, 32, 32, 32);
}